// round 13
// baseline (speedup 1.0000x reference)
#include <cuda_runtime.h>
#include <cuda_fp16.h>
#include <math.h>
#include <stdint.h>

#define N_NODES 16384
#define F_DIM   256
#define EPS_NORM 1e-12f

// ---------------- scratch (allocation-free: __device__ globals) ----------------
__device__ float  g_dinv[N_NODES];                   // 1/sqrt(deg)
__device__ __half g_Ah[(size_t)N_NODES * N_NODES];   // fp16(A), row-major (512 MB)
__device__ __half g_sfeatT[F_DIM * N_NODES];         // fp16(dinv[k]*feat[k][n]), [n][k]
__device__ __half g_aggh[N_NODES * F_DIM];           // fp16 feat_agg, [m][k] K-major
__device__ __half g_Wh[F_DIM * F_DIM];               // fp16(W^T), [n][k] K-major

// ============================ PTX helpers (sm_80+ portable) ==================
__device__ __forceinline__ uint32_t smem_to_u32(const void* p) {
    uint32_t a;
    asm("{ .reg .u64 t; cvta.to.shared.u64 t, %1; cvt.u32.u64 %0, t; }" : "=r"(a) : "l"(p));
    return a;
}

__device__ __forceinline__ uint32_t h2_bits(__half2 h) {
    return *reinterpret_cast<uint32_t*>(&h);
}

#define LDSM_X4(r0, r1, r2, r3, addr) \
    asm volatile("ldmatrix.sync.aligned.m8n8.x4.shared.b16 {%0,%1,%2,%3}, [%4];" \
        : "=r"(r0), "=r"(r1), "=r"(r2), "=r"(r3) : "r"(addr))

// fp16 MMA, fp32 accumulate: a=4 regs, b=2 regs
#define MMA_F16(d, a, b) \
    asm volatile("mma.sync.aligned.m16n8k16.row.col.f32.f16.f16.f32 " \
        "{%0,%1,%2,%3}, {%4,%5,%6,%7}, {%8,%9}, {%0,%1,%2,%3};" \
        : "+f"((d)[0]), "+f"((d)[1]), "+f"((d)[2]), "+f"((d)[3]) \
        : "r"((a)[0]), "r"((a)[1]), "r"((a)[2]), "r"((a)[3]), \
          "r"((b)[0]), "r"((b)[1]))

#define CP_ASYNC_16(dst, src) \
    asm volatile("cp.async.cg.shared.global [%0], [%1], 16;" :: "r"(dst), "l"(src))
#define CP_ASYNC_COMMIT() asm volatile("cp.async.commit_group;" ::: "memory")
#define CP_ASYNC_WAIT_1() asm volatile("cp.async.wait_group 1;" ::: "memory")
#define CP_ASYNC_WAIT_0() asm volatile("cp.async.wait_group 0;" ::: "memory")

// ---------------- kernel 1: rowsum + fp16 convert of A -----------------------
__global__ void __launch_bounds__(256) rowsum_convert_kernel(const float* __restrict__ A) {
    const int row = blockIdx.x;
    const float4* arow = reinterpret_cast<const float4*>(A + (size_t)row * N_NODES);
    uint4* hrow = reinterpret_cast<uint4*>(g_Ah + (size_t)row * N_NODES);
    const int t = threadIdx.x;
    float s = 0.f;
    #pragma unroll
    for (int j = 0; j < 8; j++) {
        int f4 = j * 512 + t * 2;
        float4 v0 = arow[f4];
        float4 v1 = arow[f4 + 1];
        s += ((v0.x + v0.y) + (v0.z + v0.w)) + ((v1.x + v1.y) + (v1.z + v1.w));
        uint4 o;
        o.x = h2_bits(__floats2half2_rn(v0.x, v0.y));
        o.y = h2_bits(__floats2half2_rn(v0.z, v0.w));
        o.z = h2_bits(__floats2half2_rn(v1.x, v1.y));
        o.w = h2_bits(__floats2half2_rn(v1.z, v1.w));
        hrow[j * 256 + t] = o;
    }
    __shared__ float red[8];
    #pragma unroll
    for (int o = 16; o > 0; o >>= 1) s += __shfl_down_sync(0xffffffffu, s, o);
    if ((t & 31) == 0) red[t >> 5] = s;
    __syncthreads();
    if (t < 32) {
        s = (t < 8) ? red[t] : 0.f;
        #pragma unroll
        for (int o = 4; o > 0; o >>= 1) s += __shfl_down_sync(0xffffffffu, s, o);
        if (t == 0) g_dinv[row] = rsqrtf(s + 1.0f);
    }
}

// ---------------- kernel 2: sfeatT[n][k] = fp16(dinv[k] * feat[k][n]) --------
__global__ void __launch_bounds__(256) transpose_scale_kernel(const float* __restrict__ feat) {
    __shared__ float tbuf[32][33];
    const int k0 = blockIdx.x * 32;
    const int n0 = blockIdx.y * 32;
    const int tx = threadIdx.x, ty = threadIdx.y;
    #pragma unroll
    for (int i = 0; i < 4; i++) {
        int k = k0 + ty + i * 8;
        tbuf[ty + i * 8][tx] = g_dinv[k] * feat[(size_t)k * F_DIM + n0 + tx];
    }
    __syncthreads();
    #pragma unroll
    for (int i = 0; i < 4; i++) {
        int n = n0 + ty + i * 8;
        g_sfeatT[(size_t)n * N_NODES + k0 + tx] = __float2half_rn(tbuf[tx][ty + i * 8]);
    }
}

// ---------------- kernel 2b: Wh[n][k] = fp16(W[k][n]) ------------------------
__global__ void __launch_bounds__(256) transpose_w_kernel(const float* __restrict__ W) {
    __shared__ float tbuf[32][33];
    const int k0 = blockIdx.x * 32;
    const int n0 = blockIdx.y * 32;
    const int tx = threadIdx.x, ty = threadIdx.y;
    #pragma unroll
    for (int i = 0; i < 4; i++) {
        int k = k0 + ty + i * 8;
        tbuf[ty + i * 8][tx] = W[(size_t)k * F_DIM + n0 + tx];
    }
    __syncthreads();
    #pragma unroll
    for (int i = 0; i < 4; i++) {
        int n = n0 + ty + i * 8;
        g_Wh[(size_t)n * F_DIM + k0 + tx] = __float2half_rn(tbuf[tx][ty + i * 8]);
    }
}

// ---------------- kernel 3: GEMM1 via mma.sync fp16 --------------------------
// C[16384,256] = Ah @ sfeatT^T (fp32 acc); aggh = fp16(dinv_i*C + dinv_i^2*feat)
// CTA tile 128x128x64, 3-stage cp.async, 8 warps (2m x 4n), warp 64x32.
// Scheduling: warp-skewed ks phases + cp.async issuance spread across ks.
#define G1_BK       64
#define G1_KT       (N_NODES / G1_BK)           /* 256 */
#define G1_ROWB     144                         /* 64 halves (128B) + 16B pad */
#define G1_TILEB    (128 * G1_ROWB)             /* 18432 per operand tile */
#define G1_STAGEB   (2 * G1_TILEB)              /* 36864 */
#define G1_SMEM     (3 * G1_STAGEB)             /* 110592 */

// quarter q of a stage load: A chunk q + B chunk q (2 cp.async per thread)
__device__ __forceinline__ void g1_load_quarter(uint32_t sbuf,
                                                const __half* __restrict__ Ah,
                                                const __half* __restrict__ BT,
                                                int m0, int n0, int k0, int tid, int q) {
    {
        int id = tid + q * 256;
        int row = id >> 3, c = id & 7;
        uint32_t dst = sbuf + row * G1_ROWB + c * 16;
        const __half* src = Ah + (size_t)(m0 + row) * N_NODES + k0 + c * 8;
        CP_ASYNC_16(dst, src);
    }
    {
        int id = tid + q * 256;
        int row = id >> 3, c = id & 7;
        uint32_t dst = sbuf + G1_TILEB + row * G1_ROWB + c * 16;
        const __half* src = BT + (size_t)(n0 + row) * N_NODES + k0 + c * 8;
        CP_ASYNC_16(dst, src);
    }
}

__device__ __forceinline__ void g1_load_stage(uint32_t sbuf,
                                              const __half* __restrict__ Ah,
                                              const __half* __restrict__ BT,
                                              int m0, int n0, int kt, int tid) {
    const int k0 = kt * G1_BK;
    #pragma unroll
    for (int q = 0; q < 4; q++)
        g1_load_quarter(sbuf, Ah, BT, m0, n0, k0, tid, q);
}

__global__ void __launch_bounds__(256, 2) gemm1_mma_kernel(const float* __restrict__ feat) {
    extern __shared__ __align__(128) char smem[];
    const uint32_t sb = smem_to_u32(smem);
    const int tid = threadIdx.x;
    const int lane = tid & 31;
    const int wid = tid >> 5;
    const int m0 = blockIdx.y * 128;
    const int n0 = blockIdx.x * 128;
    const int wm0 = (wid >> 2) * 64;   // warp m offset
    const int wn0 = (wid & 3) * 32;    // warp n offset

    float acc[4][4][4];
    #pragma unroll
    for (int i = 0; i < 4; i++)
        #pragma unroll
        for (int j = 0; j < 4; j++)
            #pragma unroll
            for (int t = 0; t < 4; t++) acc[i][j][t] = 0.f;

    uint32_t aBase0, bBase0;
    {
        const int seg = lane >> 3;
        const int rA = (lane & 7) + ((seg & 1) << 3);
        const int cA = seg >> 1;
        aBase0 = sb + (uint32_t)(wm0 + rA) * G1_ROWB + cA * 16;
        const int rB = (lane & 7) + ((seg >> 1) << 3);
        const int cB = seg & 1;
        bBase0 = sb + G1_TILEB + (uint32_t)(wn0 + rB) * G1_ROWB + cB * 16;
    }

    g1_load_stage(sb + 0 * G1_STAGEB, g_Ah, g_sfeatT, m0, n0, 0, tid);
    CP_ASYNC_COMMIT();
    g1_load_stage(sb + 1 * G1_STAGEB, g_Ah, g_sfeatT, m0, n0, 1, tid);
    CP_ASYNC_COMMIT();

    const int skew = wid & 3;          // per-warp ks phase offset
    int stage = 0;
    int ns = 2;
    #pragma unroll 1
    for (int kt = 0; kt < G1_KT; kt++) {
        CP_ASYNC_WAIT_1();
        __syncthreads();

        const int nk = kt + 2;
        const bool doload = (nk < G1_KT);
        const int nk0 = nk * G1_BK;
        const uint32_t nsbuf = sb + ns * G1_STAGEB;

        const uint32_t aAddr = aBase0 + stage * G1_STAGEB;
        const uint32_t bAddr = bBase0 + stage * G1_STAGEB;

        #pragma unroll
        for (int s = 0; s < 4; s++) {            // 4 k16-steps, warp-skewed order
            const int ks = (s + skew) & 3;
            uint32_t a[4][4], b[4][2];
            #pragma unroll
            for (int i = 0; i < 4; i++)
                LDSM_X4(a[i][0], a[i][1], a[i][2], a[i][3],
                        aAddr + i * (16 * G1_ROWB) + ks * 32);
            #pragma unroll
            for (int j = 0; j < 2; j++)
                LDSM_X4(b[2 * j][0], b[2 * j][1], b[2 * j + 1][0], b[2 * j + 1][1],
                        bAddr + j * (16 * G1_ROWB) + ks * 32);
            // fill the LDSM->MMA latency window with independent load issue
            if (doload)
                g1_load_quarter(nsbuf, g_Ah, g_sfeatT, m0, n0, nk0, tid, s);
            #pragma unroll
            for (int i = 0; i < 4; i++)
                #pragma unroll
                for (int j = 0; j < 4; j++)
                    MMA_F16(acc[i][j], a[i], b[j]);
        }
        CP_ASYNC_COMMIT();

        stage++; if (stage == 3) stage = 0;
        ns++;    if (ns == 3)    ns = 0;
    }

    // epilogue: aggh = fp16(dinv_m * acc + dinv_m^2 * feat)  (identity exact fp32)
    const int r = lane >> 2;
    const int c2 = (lane & 3) * 2;
    #pragma unroll
    for (int i = 0; i < 4; i++) {
        #pragma unroll
        for (int half = 0; half < 2; half++) {
            const int m = m0 + wm0 + i * 16 + r + half * 8;
            const float di = g_dinv[m];
            const float di2 = di * di;
            #pragma unroll
            for (int j = 0; j < 4; j++) {
                const int n = n0 + wn0 + j * 8 + c2;
                float2 fv = *reinterpret_cast<const float2*>(&feat[(size_t)m * F_DIM + n]);
                float ox = di * acc[i][j][half * 2 + 0] + di2 * fv.x;
                float oy = di * acc[i][j][half * 2 + 1] + di2 * fv.y;
                *reinterpret_cast<uint32_t*>(&g_aggh[(size_t)m * F_DIM + n]) =
                    h2_bits(__floats2half2_rn(ox, oy));
            }
        }
    }
}

// ---------------- kernel 4: out = l2norm_rows(relu(aggh @ Wh^T)) -------------
// fp16 mma.sync: BM=64, BN=256 (full row), BK=64 over K=256 (4 kt).
// 2 stages, prefetch distance 1.
#define G2_BK      64
#define G2_KT      (F_DIM / G2_BK)              /* 4 */
#define G2_ROWB    144
#define G2_TILEA   (64 * G2_ROWB)               /* 9216 */
#define G2_TILEB   (256 * G2_ROWB)              /* 36864 */
#define G2_STAGEB  (G2_TILEA + G2_TILEB)        /* 46080 */
#define G2_SMEM    (2 * G2_STAGEB + 256)        /* 92416 (incl ssq) */

__device__ __forceinline__ void g2_load_stage(uint32_t sbuf, int m0, int kt, int tid) {
    const int k0 = kt * G2_BK;
    #pragma unroll
    for (int i = 0; i < 2; i++) {
        int id = tid + i * 256;
        int row = id >> 3, c = id & 7;
        uint32_t dst = sbuf + row * G2_ROWB + c * 16;
        const __half* src = g_aggh + (size_t)(m0 + row) * F_DIM + k0 + c * 8;
        CP_ASYNC_16(dst, src);
    }
    #pragma unroll
    for (int i = 0; i < 8; i++) {
        int id = tid + i * 256;
        int row = id >> 3, c = id & 7;
        uint32_t dst = sbuf + G2_TILEA + row * G2_ROWB + c * 16;
        const __half* src = g_Wh + (size_t)row * F_DIM + k0 + c * 8;
        CP_ASYNC_16(dst, src);
    }
}

__global__ void __launch_bounds__(256, 2) gemm2h_norm_kernel(float* __restrict__ out) {
    extern __shared__ __align__(128) char smem[];
    const uint32_t sb = smem_to_u32(smem);
    float* s_ssq = reinterpret_cast<float*>(smem + 2 * G2_STAGEB);
    const int tid = threadIdx.x;
    const int lane = tid & 31;
    const int wid = tid >> 5;
    const int m0 = blockIdx.x * 64;
    const int wm0 = (wid >> 2) * 32;   // 0,32
    const int wn0 = (wid & 3) * 64;    // 0,64,128,192

    if (tid < 64) s_ssq[tid] = 0.f;

    float acc[2][8][4];
    #pragma unroll
    for (int i = 0; i < 2; i++)
        #pragma unroll
        for (int j = 0; j < 8; j++)
            #pragma unroll
            for (int t = 0; t < 4; t++) acc[i][j][t] = 0.f;

    uint32_t aBase0, bBase0;
    {
        const int seg = lane >> 3;
        const int rA = (lane & 7) + ((seg & 1) << 3);
        const int cA = seg >> 1;
        aBase0 = sb + (uint32_t)(wm0 + rA) * G2_ROWB + cA * 16;
        const int rB = (lane & 7) + ((seg >> 1) << 3);
        const int cB = seg & 1;
        bBase0 = sb + G2_TILEA + (uint32_t)(wn0 + rB) * G2_ROWB + cB * 16;
    }

    g2_load_stage(sb + 0 * G2_STAGEB, m0, 0, tid);
    CP_ASYNC_COMMIT();

    #pragma unroll
    for (int kt = 0; kt < G2_KT; kt++) {
        CP_ASYNC_WAIT_0();       // buffer kt&1 fully loaded
        __syncthreads();         // all warps done with buffer (kt+1)&1

        const int nk = kt + 1;
        if (nk < G2_KT) {
            g2_load_stage(sb + (nk & 1) * G2_STAGEB, m0, nk, tid);
            CP_ASYNC_COMMIT();
        }

        const uint32_t aAddr = aBase0 + (kt & 1) * G2_STAGEB;
        const uint32_t bAddr = bBase0 + (kt & 1) * G2_STAGEB;

        #pragma unroll
        for (int ks = 0; ks < 4; ks++) {
            uint32_t a[2][4], b[8][2];
            #pragma unroll
            for (int i = 0; i < 2; i++)
                LDSM_X4(a[i][0], a[i][1], a[i][2], a[i][3],
                        aAddr + i * (16 * G2_ROWB) + ks * 32);
            #pragma unroll
            for (int j = 0; j < 4; j++)
                LDSM_X4(b[2 * j][0], b[2 * j][1], b[2 * j + 1][0], b[2 * j + 1][1],
                        bAddr + j * (16 * G2_ROWB) + ks * 32);
            #pragma unroll
            for (int i = 0; i < 2; i++)
                #pragma unroll
                for (int j = 0; j < 8; j++)
                    MMA_F16(acc[i][j], a[i], b[j]);
        }
    }

    // relu + per-row ssq partials
    const int r = lane >> 2;
    #pragma unroll
    for (int i = 0; i < 2; i++) {
        #pragma unroll
        for (int half = 0; half < 2; half++) {
            float p = 0.f;
            #pragma unroll
            for (int j = 0; j < 8; j++) {
                float v0 = fmaxf(acc[i][j][half * 2 + 0], 0.f);
                float v1 = fmaxf(acc[i][j][half * 2 + 1], 0.f);
                acc[i][j][half * 2 + 0] = v0;
                acc[i][j][half * 2 + 1] = v1;
                p = fmaf(v0, v0, fmaf(v1, v1, p));
            }
            p += __shfl_xor_sync(0xffffffffu, p, 1);
            p += __shfl_xor_sync(0xffffffffu, p, 2);
            if ((lane & 3) == 0)
                atomicAdd(&s_ssq[wm0 + i * 16 + r + half * 8], p);
        }
    }
    __syncthreads();

    // normalize + write
    const int c2 = (lane & 3) * 2;
    #pragma unroll
    for (int i = 0; i < 2; i++) {
        #pragma unroll
        for (int half = 0; half < 2; half++) {
            const int ml = wm0 + i * 16 + r + half * 8;
            const int m = m0 + ml;
            float nrm = sqrtf(s_ssq[ml]);
            float sc = 1.0f / fmaxf(nrm, EPS_NORM);
            #pragma unroll
            for (int j = 0; j < 8; j++) {
                const int n = wn0 + j * 8 + c2;
                float2 o;
                o.x = acc[i][j][half * 2 + 0] * sc;
                o.y = acc[i][j][half * 2 + 1] * sc;
                *reinterpret_cast<float2*>(&out[(size_t)m * F_DIM + n]) = o;
            }
        }
    }
}

// ---------------- host launch -------------------------------------------------
extern "C" void kernel_launch(void* const* d_in, const int* in_sizes, int n_in,
                              void* d_out, int out_size) {
    const float* feat = nullptr;
    const float* A = nullptr;
    const float* W = nullptr;
    for (int i = 0; i < n_in; i++) {
        long long sz = (long long)in_sizes[i];
        if (sz == (long long)N_NODES * N_NODES)      A    = (const float*)d_in[i];
        else if (sz == (long long)N_NODES * F_DIM)   feat = (const float*)d_in[i];
        else if (sz == (long long)F_DIM * F_DIM)     W    = (const float*)d_in[i];
    }
    float* out = (float*)d_out;

    static bool attr_set = false;
    if (!attr_set) {
        cudaFuncSetAttribute(gemm1_mma_kernel,
                             cudaFuncAttributeMaxDynamicSharedMemorySize, G1_SMEM);
        cudaFuncSetAttribute(gemm2h_norm_kernel,
                             cudaFuncAttributeMaxDynamicSharedMemorySize, G2_SMEM);
        attr_set = true;
    }

    // 1. degrees -> dinv, plus A -> fp16 copy
    rowsum_convert_kernel<<<N_NODES, 256>>>(A);
    // 2. transposed, dinv-scaled fp16 features (B operand) + fp16 W^T
    {
        dim3 grid(N_NODES / 32, F_DIM / 32);
        transpose_scale_kernel<<<grid, dim3(32, 8)>>>(feat);
    }
    {
        dim3 grid(F_DIM / 32, F_DIM / 32);
        transpose_w_kernel<<<grid, dim3(32, 8)>>>(W);
    }
    // 3. fp16 tensor-core GEMM (128x128 tiles) + fused fp16 epilogue
    {
        dim3 grid(F_DIM / 128, N_NODES / 128);   // (2, 128) = 256 CTAs, 2/SM
        gemm1_mma_kernel<<<grid, 256, G1_SMEM>>>(feat);
    }
    // 4. fp16 projection + relu + row L2 normalize
    gemm2h_norm_kernel<<<N_NODES / 64, 256, G2_SMEM>>>(out);
}

// round 14
// speedup vs baseline: 1.2227x; 1.2227x over previous
#include <cuda_runtime.h>
#include <cuda_fp16.h>
#include <math.h>
#include <stdint.h>

#define N_NODES 16384
#define F_DIM   256
#define EPS_NORM 1e-12f

// ---------------- scratch (allocation-free: __device__ globals) ----------------
__device__ float  g_dinv[N_NODES];                   // 1/sqrt(deg)
__device__ __half g_Ah[(size_t)N_NODES * N_NODES];   // fp16(A), row-major (512 MB)
__device__ __half g_sfeatT[F_DIM * N_NODES];         // fp16(dinv[k]*feat[k][n]), [n][k]
__device__ __half g_aggh[N_NODES * F_DIM];           // fp16 feat_agg, [m][k] K-major
__device__ __half g_Wh[F_DIM * F_DIM];               // fp16(W^T), [n][k] K-major

// ============================ PTX helpers (sm_80+ portable) ==================
__device__ __forceinline__ uint32_t smem_to_u32(const void* p) {
    uint32_t a;
    asm("{ .reg .u64 t; cvta.to.shared.u64 t, %1; cvt.u32.u64 %0, t; }" : "=r"(a) : "l"(p));
    return a;
}

__device__ __forceinline__ uint32_t h2_bits(__half2 h) {
    return *reinterpret_cast<uint32_t*>(&h);
}

#define LDSM_X4(r0, r1, r2, r3, addr) \
    asm volatile("ldmatrix.sync.aligned.m8n8.x4.shared.b16 {%0,%1,%2,%3}, [%4];" \
        : "=r"(r0), "=r"(r1), "=r"(r2), "=r"(r3) : "r"(addr))

// fp16 MMA, fp32 accumulate: a=4 regs, b=2 regs
#define MMA_F16(d, a, b) \
    asm volatile("mma.sync.aligned.m16n8k16.row.col.f32.f16.f16.f32 " \
        "{%0,%1,%2,%3}, {%4,%5,%6,%7}, {%8,%9}, {%0,%1,%2,%3};" \
        : "+f"((d)[0]), "+f"((d)[1]), "+f"((d)[2]), "+f"((d)[3]) \
        : "r"((a)[0]), "r"((a)[1]), "r"((a)[2]), "r"((a)[3]), \
          "r"((b)[0]), "r"((b)[1]))

#define CP_ASYNC_16(dst, src) \
    asm volatile("cp.async.cg.shared.global [%0], [%1], 16;" :: "r"(dst), "l"(src))
#define CP_ASYNC_COMMIT() asm volatile("cp.async.commit_group;" ::: "memory")
#define CP_ASYNC_WAIT_1() asm volatile("cp.async.wait_group 1;" ::: "memory")
#define CP_ASYNC_WAIT_0() asm volatile("cp.async.wait_group 0;" ::: "memory")

// ---------------- kernel 1: rowsum + fp16 convert of A -----------------------
__global__ void __launch_bounds__(256) rowsum_convert_kernel(const float* __restrict__ A) {
    const int row = blockIdx.x;
    const float4* arow = reinterpret_cast<const float4*>(A + (size_t)row * N_NODES);
    uint4* hrow = reinterpret_cast<uint4*>(g_Ah + (size_t)row * N_NODES);
    const int t = threadIdx.x;
    float s = 0.f;
    #pragma unroll
    for (int j = 0; j < 8; j++) {
        int f4 = j * 512 + t * 2;
        float4 v0 = arow[f4];
        float4 v1 = arow[f4 + 1];
        s += ((v0.x + v0.y) + (v0.z + v0.w)) + ((v1.x + v1.y) + (v1.z + v1.w));
        uint4 o;
        o.x = h2_bits(__floats2half2_rn(v0.x, v0.y));
        o.y = h2_bits(__floats2half2_rn(v0.z, v0.w));
        o.z = h2_bits(__floats2half2_rn(v1.x, v1.y));
        o.w = h2_bits(__floats2half2_rn(v1.z, v1.w));
        hrow[j * 256 + t] = o;
    }
    __shared__ float red[8];
    #pragma unroll
    for (int o = 16; o > 0; o >>= 1) s += __shfl_down_sync(0xffffffffu, s, o);
    if ((t & 31) == 0) red[t >> 5] = s;
    __syncthreads();
    if (t < 32) {
        s = (t < 8) ? red[t] : 0.f;
        #pragma unroll
        for (int o = 4; o > 0; o >>= 1) s += __shfl_down_sync(0xffffffffu, s, o);
        if (t == 0) g_dinv[row] = rsqrtf(s + 1.0f);
    }
}

// ---------------- kernel 2: merged transposes --------------------------------
// z == 0: sfeatT[n][k] = fp16(dinv[k] * feat[k][n])   (grid x: K/32, y: F/32)
// z == 1: Wh[n][k]     = fp16(W[k][n])                (only first F/32 x-blocks)
__global__ void __launch_bounds__(256) transpose_all_kernel(const float* __restrict__ feat,
                                                            const float* __restrict__ W) {
    __shared__ float tbuf[32][33];
    const int z  = blockIdx.z;
    const int k0 = blockIdx.x * 32;
    const int n0 = blockIdx.y * 32;
    const int tx = threadIdx.x, ty = threadIdx.y;
    if (z == 0) {
        #pragma unroll
        for (int i = 0; i < 4; i++) {
            int k = k0 + ty + i * 8;
            tbuf[ty + i * 8][tx] = g_dinv[k] * feat[(size_t)k * F_DIM + n0 + tx];
        }
        __syncthreads();
        #pragma unroll
        for (int i = 0; i < 4; i++) {
            int n = n0 + ty + i * 8;
            g_sfeatT[(size_t)n * N_NODES + k0 + tx] = __float2half_rn(tbuf[tx][ty + i * 8]);
        }
    } else {
        if (k0 >= F_DIM) return;
        #pragma unroll
        for (int i = 0; i < 4; i++) {
            int k = k0 + ty + i * 8;
            tbuf[ty + i * 8][tx] = W[(size_t)k * F_DIM + n0 + tx];
        }
        __syncthreads();
        #pragma unroll
        for (int i = 0; i < 4; i++) {
            int n = n0 + ty + i * 8;
            g_Wh[(size_t)n * F_DIM + k0 + tx] = __float2half_rn(tbuf[tx][ty + i * 8]);
        }
    }
}

// ---------------- kernel 3: GEMM1 via mma.sync fp16 (R12 verbatim) -----------
// C[16384,256] = Ah @ sfeatT^T (fp32 acc); aggh = fp16(dinv_i*C + dinv_i^2*feat)
// CTA tile 128x128x64, 3-stage cp.async, 8 warps (2m x 4n), warp 64x32.
#define G1_BK       64
#define G1_KT       (N_NODES / G1_BK)           /* 256 */
#define G1_ROWB     144                         /* 64 halves (128B) + 16B pad */
#define G1_TILEB    (128 * G1_ROWB)             /* 18432 per operand tile */
#define G1_STAGEB   (2 * G1_TILEB)              /* 36864 */
#define G1_SMEM     (3 * G1_STAGEB)             /* 110592 */

__device__ __forceinline__ void g1_load_stage(uint32_t sbuf,
                                              const __half* __restrict__ Ah,
                                              const __half* __restrict__ BT,
                                              int m0, int n0, int kt, int tid) {
    const int k0 = kt * G1_BK;
    #pragma unroll
    for (int i = 0; i < 4; i++) {
        int id = tid + i * 256;
        int row = id >> 3, c = id & 7;
        uint32_t dst = sbuf + row * G1_ROWB + c * 16;
        const __half* src = Ah + (size_t)(m0 + row) * N_NODES + k0 + c * 8;
        CP_ASYNC_16(dst, src);
    }
    #pragma unroll
    for (int i = 0; i < 4; i++) {
        int id = tid + i * 256;
        int row = id >> 3, c = id & 7;
        uint32_t dst = sbuf + G1_TILEB + row * G1_ROWB + c * 16;
        const __half* src = BT + (size_t)(n0 + row) * N_NODES + k0 + c * 8;
        CP_ASYNC_16(dst, src);
    }
}

__global__ void __launch_bounds__(256, 2) gemm1_mma_kernel(const float* __restrict__ feat) {
    extern __shared__ __align__(128) char smem[];
    const uint32_t sb = smem_to_u32(smem);
    const int tid = threadIdx.x;
    const int lane = tid & 31;
    const int wid = tid >> 5;
    const int m0 = blockIdx.y * 128;
    const int n0 = blockIdx.x * 128;
    const int wm0 = (wid >> 2) * 64;   // warp m offset
    const int wn0 = (wid & 3) * 32;    // warp n offset

    float acc[4][4][4];
    #pragma unroll
    for (int i = 0; i < 4; i++)
        #pragma unroll
        for (int j = 0; j < 4; j++)
            #pragma unroll
            for (int t = 0; t < 4; t++) acc[i][j][t] = 0.f;

    uint32_t aBase0, bBase0;
    {
        const int seg = lane >> 3;
        const int rA = (lane & 7) + ((seg & 1) << 3);
        const int cA = seg >> 1;
        aBase0 = sb + (uint32_t)(wm0 + rA) * G1_ROWB + cA * 16;
        const int rB = (lane & 7) + ((seg >> 1) << 3);
        const int cB = seg & 1;
        bBase0 = sb + G1_TILEB + (uint32_t)(wn0 + rB) * G1_ROWB + cB * 16;
    }

    g1_load_stage(sb + 0 * G1_STAGEB, g_Ah, g_sfeatT, m0, n0, 0, tid);
    CP_ASYNC_COMMIT();
    g1_load_stage(sb + 1 * G1_STAGEB, g_Ah, g_sfeatT, m0, n0, 1, tid);
    CP_ASYNC_COMMIT();

    int stage = 0;
    int ns = 2;
    #pragma unroll 1
    for (int kt = 0; kt < G1_KT; kt++) {
        CP_ASYNC_WAIT_1();
        __syncthreads();

        const int nk = kt + 2;
        if (nk < G1_KT)
            g1_load_stage(sb + ns * G1_STAGEB, g_Ah, g_sfeatT, m0, n0, nk, tid);
        CP_ASYNC_COMMIT();

        const uint32_t aAddr = aBase0 + stage * G1_STAGEB;
        const uint32_t bAddr = bBase0 + stage * G1_STAGEB;

        #pragma unroll
        for (int ks = 0; ks < 4; ks++) {         // 4 k16-steps per kt(64)
            uint32_t a[4][4], b[4][2];
            #pragma unroll
            for (int i = 0; i < 4; i++)
                LDSM_X4(a[i][0], a[i][1], a[i][2], a[i][3],
                        aAddr + i * (16 * G1_ROWB) + ks * 32);
            #pragma unroll
            for (int j = 0; j < 2; j++)
                LDSM_X4(b[2 * j][0], b[2 * j][1], b[2 * j + 1][0], b[2 * j + 1][1],
                        bAddr + j * (16 * G1_ROWB) + ks * 32);
            #pragma unroll
            for (int i = 0; i < 4; i++)
                #pragma unroll
                for (int j = 0; j < 4; j++)
                    MMA_F16(acc[i][j], a[i], b[j]);
        }

        stage++; if (stage == 3) stage = 0;
        ns++;    if (ns == 3)    ns = 0;
    }

    // epilogue: aggh = fp16(dinv_m * acc + dinv_m^2 * feat)  (identity exact fp32)
    const int r = lane >> 2;
    const int c2 = (lane & 3) * 2;
    #pragma unroll
    for (int i = 0; i < 4; i++) {
        #pragma unroll
        for (int half = 0; half < 2; half++) {
            const int m = m0 + wm0 + i * 16 + r + half * 8;
            const float di = g_dinv[m];
            const float di2 = di * di;
            #pragma unroll
            for (int j = 0; j < 4; j++) {
                const int n = n0 + wn0 + j * 8 + c2;
                float2 fv = *reinterpret_cast<const float2*>(&feat[(size_t)m * F_DIM + n]);
                float ox = di * acc[i][j][half * 2 + 0] + di2 * fv.x;
                float oy = di * acc[i][j][half * 2 + 1] + di2 * fv.y;
                *reinterpret_cast<uint32_t*>(&g_aggh[(size_t)m * F_DIM + n]) =
                    h2_bits(__floats2half2_rn(ox, oy));
            }
        }
    }
}

// ---------------- kernel 4: out = l2norm_rows(relu(aggh @ Wh^T)) -------------
// fp16 mma.sync: BM=64, BN=256 (full row), BK=64 over K=256 (4 kt).
// 2 stages, prefetch distance 1.
#define G2_BK      64
#define G2_KT      (F_DIM / G2_BK)              /* 4 */
#define G2_ROWB    144
#define G2_TILEA   (64 * G2_ROWB)               /* 9216 */
#define G2_TILEB   (256 * G2_ROWB)              /* 36864 */
#define G2_STAGEB  (G2_TILEA + G2_TILEB)        /* 46080 */
#define G2_SMEM    (2 * G2_STAGEB + 256)        /* 92416 (incl ssq) */

__device__ __forceinline__ void g2_load_stage(uint32_t sbuf, int m0, int kt, int tid) {
    const int k0 = kt * G2_BK;
    #pragma unroll
    for (int i = 0; i < 2; i++) {
        int id = tid + i * 256;
        int row = id >> 3, c = id & 7;
        uint32_t dst = sbuf + row * G2_ROWB + c * 16;
        const __half* src = g_aggh + (size_t)(m0 + row) * F_DIM + k0 + c * 8;
        CP_ASYNC_16(dst, src);
    }
    #pragma unroll
    for (int i = 0; i < 8; i++) {
        int id = tid + i * 256;
        int row = id >> 3, c = id & 7;
        uint32_t dst = sbuf + G2_TILEA + row * G2_ROWB + c * 16;
        const __half* src = g_Wh + (size_t)row * F_DIM + k0 + c * 8;
        CP_ASYNC_16(dst, src);
    }
}

__global__ void __launch_bounds__(256, 2) gemm2h_norm_kernel(float* __restrict__ out) {
    extern __shared__ __align__(128) char smem[];
    const uint32_t sb = smem_to_u32(smem);
    float* s_ssq = reinterpret_cast<float*>(smem + 2 * G2_STAGEB);
    const int tid = threadIdx.x;
    const int lane = tid & 31;
    const int wid = tid >> 5;
    const int m0 = blockIdx.x * 64;
    const int wm0 = (wid >> 2) * 32;   // 0,32
    const int wn0 = (wid & 3) * 64;    // 0,64,128,192

    if (tid < 64) s_ssq[tid] = 0.f;

    float acc[2][8][4];
    #pragma unroll
    for (int i = 0; i < 2; i++)
        #pragma unroll
        for (int j = 0; j < 8; j++)
            #pragma unroll
            for (int t = 0; t < 4; t++) acc[i][j][t] = 0.f;

    uint32_t aBase0, bBase0;
    {
        const int seg = lane >> 3;
        const int rA = (lane & 7) + ((seg & 1) << 3);
        const int cA = seg >> 1;
        aBase0 = sb + (uint32_t)(wm0 + rA) * G2_ROWB + cA * 16;
        const int rB = (lane & 7) + ((seg >> 1) << 3);
        const int cB = seg & 1;
        bBase0 = sb + G2_TILEA + (uint32_t)(wn0 + rB) * G2_ROWB + cB * 16;
    }

    g2_load_stage(sb + 0 * G2_STAGEB, m0, 0, tid);
    CP_ASYNC_COMMIT();

    #pragma unroll
    for (int kt = 0; kt < G2_KT; kt++) {
        CP_ASYNC_WAIT_0();       // buffer kt&1 fully loaded
        __syncthreads();         // all warps done with buffer (kt+1)&1

        const int nk = kt + 1;
        if (nk < G2_KT) {
            g2_load_stage(sb + (nk & 1) * G2_STAGEB, m0, nk, tid);
            CP_ASYNC_COMMIT();
        }

        const uint32_t aAddr = aBase0 + (kt & 1) * G2_STAGEB;
        const uint32_t bAddr = bBase0 + (kt & 1) * G2_STAGEB;

        #pragma unroll
        for (int ks = 0; ks < 4; ks++) {
            uint32_t a[2][4], b[8][2];
            #pragma unroll
            for (int i = 0; i < 2; i++)
                LDSM_X4(a[i][0], a[i][1], a[i][2], a[i][3],
                        aAddr + i * (16 * G2_ROWB) + ks * 32);
            #pragma unroll
            for (int j = 0; j < 4; j++)
                LDSM_X4(b[2 * j][0], b[2 * j][1], b[2 * j + 1][0], b[2 * j + 1][1],
                        bAddr + j * (16 * G2_ROWB) + ks * 32);
            #pragma unroll
            for (int i = 0; i < 2; i++)
                #pragma unroll
                for (int j = 0; j < 8; j++)
                    MMA_F16(acc[i][j], a[i], b[j]);
        }
    }

    // relu + per-row ssq partials
    const int r = lane >> 2;
    #pragma unroll
    for (int i = 0; i < 2; i++) {
        #pragma unroll
        for (int half = 0; half < 2; half++) {
            float p = 0.f;
            #pragma unroll
            for (int j = 0; j < 8; j++) {
                float v0 = fmaxf(acc[i][j][half * 2 + 0], 0.f);
                float v1 = fmaxf(acc[i][j][half * 2 + 1], 0.f);
                acc[i][j][half * 2 + 0] = v0;
                acc[i][j][half * 2 + 1] = v1;
                p = fmaf(v0, v0, fmaf(v1, v1, p));
            }
            p += __shfl_xor_sync(0xffffffffu, p, 1);
            p += __shfl_xor_sync(0xffffffffu, p, 2);
            if ((lane & 3) == 0)
                atomicAdd(&s_ssq[wm0 + i * 16 + r + half * 8], p);
        }
    }
    __syncthreads();

    // normalize + write
    const int c2 = (lane & 3) * 2;
    #pragma unroll
    for (int i = 0; i < 2; i++) {
        #pragma unroll
        for (int half = 0; half < 2; half++) {
            const int ml = wm0 + i * 16 + r + half * 8;
            const int m = m0 + ml;
            float nrm = sqrtf(s_ssq[ml]);
            float sc = 1.0f / fmaxf(nrm, EPS_NORM);
            #pragma unroll
            for (int j = 0; j < 8; j++) {
                const int n = wn0 + j * 8 + c2;
                float2 o;
                o.x = acc[i][j][half * 2 + 0] * sc;
                o.y = acc[i][j][half * 2 + 1] * sc;
                *reinterpret_cast<float2*>(&out[(size_t)m * F_DIM + n]) = o;
            }
        }
    }
}

// ---------------- host launch -------------------------------------------------
extern "C" void kernel_launch(void* const* d_in, const int* in_sizes, int n_in,
                              void* d_out, int out_size) {
    const float* feat = nullptr;
    const float* A = nullptr;
    const float* W = nullptr;
    for (int i = 0; i < n_in; i++) {
        long long sz = (long long)in_sizes[i];
        if (sz == (long long)N_NODES * N_NODES)      A    = (const float*)d_in[i];
        else if (sz == (long long)N_NODES * F_DIM)   feat = (const float*)d_in[i];
        else if (sz == (long long)F_DIM * F_DIM)     W    = (const float*)d_in[i];
    }
    float* out = (float*)d_out;

    static bool attr_set = false;
    if (!attr_set) {
        cudaFuncSetAttribute(gemm1_mma_kernel,
                             cudaFuncAttributeMaxDynamicSharedMemorySize, G1_SMEM);
        cudaFuncSetAttribute(gemm2h_norm_kernel,
                             cudaFuncAttributeMaxDynamicSharedMemorySize, G2_SMEM);
        attr_set = true;
    }

    // 1. degrees -> dinv, plus A -> fp16 copy
    rowsum_convert_kernel<<<N_NODES, 256>>>(A);
    // 2. merged transposes: z=0 feat (scaled), z=1 W
    {
        dim3 grid(N_NODES / 32, F_DIM / 32, 2);  // z=1 uses only x < F_DIM/32
        transpose_all_kernel<<<grid, dim3(32, 8)>>>(feat, W);
    }
    // 3. fp16 tensor-core GEMM (128x128 tiles, R12 config) + fused fp16 epilogue
    {
        dim3 grid(F_DIM / 128, N_NODES / 128);   // (2, 128) = 256 CTAs, 2/SM
        gemm1_mma_kernel<<<grid, 256, G1_SMEM>>>(feat);
    }
    // 4. fp16 projection + relu + row L2 normalize
    gemm2h_norm_kernel<<<N_NODES / 64, 256, G2_SMEM>>>(out);
}

// round 15
// speedup vs baseline: 1.3113x; 1.0724x over previous
#include <cuda_runtime.h>
#include <cuda_fp16.h>
#include <math.h>
#include <stdint.h>

#define N_NODES 16384
#define F_DIM   256
#define EPS_NORM 1e-12f

// ---------------- scratch (allocation-free: __device__ globals) ----------------
__device__ float  g_dinv[N_NODES];                   // 1/sqrt(deg)
__device__ __half g_Ah[(size_t)N_NODES * N_NODES];   // fp16(A), row-major (512 MB)
__device__ __half g_sfeatT[F_DIM * N_NODES];         // fp16(dinv[k]*feat[k][n]), [n][k]
__device__ __half g_aggh[N_NODES * F_DIM];           // fp16 feat_agg, [m][k] K-major
__device__ __half g_Wh[F_DIM * F_DIM];               // fp16(W^T), [n][k] K-major
// split-K partial sums: up to 320 pieces x 2 segments x 128x128 fp32 tile
#define MAX_PIECES 320
__device__ float  g_part[(size_t)MAX_PIECES * 2 * 16384];

// ============================ PTX helpers (sm_80+ portable) ==================
__device__ __forceinline__ uint32_t smem_to_u32(const void* p) {
    uint32_t a;
    asm("{ .reg .u64 t; cvta.to.shared.u64 t, %1; cvt.u32.u64 %0, t; }" : "=r"(a) : "l"(p));
    return a;
}

__device__ __forceinline__ uint32_t h2_bits(__half2 h) {
    return *reinterpret_cast<uint32_t*>(&h);
}

#define LDSM_X4(r0, r1, r2, r3, addr) \
    asm volatile("ldmatrix.sync.aligned.m8n8.x4.shared.b16 {%0,%1,%2,%3}, [%4];" \
        : "=r"(r0), "=r"(r1), "=r"(r2), "=r"(r3) : "r"(addr))

#define MMA_F16(d, a, b) \
    asm volatile("mma.sync.aligned.m16n8k16.row.col.f32.f16.f16.f32 " \
        "{%0,%1,%2,%3}, {%4,%5,%6,%7}, {%8,%9}, {%0,%1,%2,%3};" \
        : "+f"((d)[0]), "+f"((d)[1]), "+f"((d)[2]), "+f"((d)[3]) \
        : "r"((a)[0]), "r"((a)[1]), "r"((a)[2]), "r"((a)[3]), \
          "r"((b)[0]), "r"((b)[1]))

#define CP_ASYNC_16(dst, src) \
    asm volatile("cp.async.cg.shared.global [%0], [%1], 16;" :: "r"(dst), "l"(src))
#define CP_ASYNC_COMMIT() asm volatile("cp.async.commit_group;" ::: "memory")
#define CP_ASYNC_WAIT_1() asm volatile("cp.async.wait_group 1;" ::: "memory")
#define CP_ASYNC_WAIT_0() asm volatile("cp.async.wait_group 0;" ::: "memory")

// ---------------- kernel 1: rowsum + fp16 convert of A -----------------------
__global__ void __launch_bounds__(256) rowsum_convert_kernel(const float* __restrict__ A) {
    const int row = blockIdx.x;
    const float4* arow = reinterpret_cast<const float4*>(A + (size_t)row * N_NODES);
    uint4* hrow = reinterpret_cast<uint4*>(g_Ah + (size_t)row * N_NODES);
    const int t = threadIdx.x;
    float s = 0.f;
    #pragma unroll
    for (int j = 0; j < 8; j++) {
        int f4 = j * 512 + t * 2;
        float4 v0 = arow[f4];
        float4 v1 = arow[f4 + 1];
        s += ((v0.x + v0.y) + (v0.z + v0.w)) + ((v1.x + v1.y) + (v1.z + v1.w));
        uint4 o;
        o.x = h2_bits(__floats2half2_rn(v0.x, v0.y));
        o.y = h2_bits(__floats2half2_rn(v0.z, v0.w));
        o.z = h2_bits(__floats2half2_rn(v1.x, v1.y));
        o.w = h2_bits(__floats2half2_rn(v1.z, v1.w));
        hrow[j * 256 + t] = o;
    }
    __shared__ float red[8];
    #pragma unroll
    for (int o = 16; o > 0; o >>= 1) s += __shfl_down_sync(0xffffffffu, s, o);
    if ((t & 31) == 0) red[t >> 5] = s;
    __syncthreads();
    if (t < 32) {
        s = (t < 8) ? red[t] : 0.f;
        #pragma unroll
        for (int o = 4; o > 0; o >>= 1) s += __shfl_down_sync(0xffffffffu, s, o);
        if (t == 0) g_dinv[row] = rsqrtf(s + 1.0f);
    }
}

// ---------------- kernel 2: merged transposes --------------------------------
__global__ void __launch_bounds__(256) transpose_all_kernel(const float* __restrict__ feat,
                                                            const float* __restrict__ W) {
    __shared__ float tbuf[32][33];
    const int z  = blockIdx.z;
    const int k0 = blockIdx.x * 32;
    const int n0 = blockIdx.y * 32;
    const int tx = threadIdx.x, ty = threadIdx.y;
    if (z == 0) {
        #pragma unroll
        for (int i = 0; i < 4; i++) {
            int k = k0 + ty + i * 8;
            tbuf[ty + i * 8][tx] = g_dinv[k] * feat[(size_t)k * F_DIM + n0 + tx];
        }
        __syncthreads();
        #pragma unroll
        for (int i = 0; i < 4; i++) {
            int n = n0 + ty + i * 8;
            g_sfeatT[(size_t)n * N_NODES + k0 + tx] = __float2half_rn(tbuf[tx][ty + i * 8]);
        }
    } else {
        if (k0 >= F_DIM) return;
        #pragma unroll
        for (int i = 0; i < 4; i++) {
            int k = k0 + ty + i * 8;
            tbuf[ty + i * 8][tx] = W[(size_t)k * F_DIM + n0 + tx];
        }
        __syncthreads();
        #pragma unroll
        for (int i = 0; i < 4; i++) {
            int n = n0 + ty + i * 8;
            g_Wh[(size_t)n * F_DIM + k0 + tx] = __float2half_rn(tbuf[tx][ty + i * 8]);
        }
    }
}

// ---------------- kernel 3: GEMM1 pieces (continuous split-K packing) --------
// Global iteration space: 256 tiles (t = tm*2 + tn, tile 128x128) x 256 kt.
// Piece p handles global kt range [p*S, (p+1)*S), S <= 256 -> spans <= 2 tiles.
// Per segment: 3-stage cp.async pipeline; fp32 partials to g_part[p][seg].
#define G1_BK       64
#define G1_ROWB     144                         /* 64 halves (128B) + 16B pad */
#define G1_TILEB    (128 * G1_ROWB)             /* 18432 per operand tile */
#define G1_STAGEB   (2 * G1_TILEB)              /* 36864 */
#define G1_SMEM     (3 * G1_STAGEB)             /* 110592 */
#define G1_GKT      (256 * 256)                 /* 65536 global kt units */

__device__ __forceinline__ void g1_load_stage(uint32_t sbuf, int m0, int n0, int kt, int tid) {
    const int k0 = kt * G1_BK;
    #pragma unroll
    for (int i = 0; i < 4; i++) {
        int id = tid + i * 256;
        int row = id >> 3, c = id & 7;
        uint32_t dst = sbuf + row * G1_ROWB + c * 16;
        const __half* src = g_Ah + (size_t)(m0 + row) * N_NODES + k0 + c * 8;
        CP_ASYNC_16(dst, src);
    }
    #pragma unroll
    for (int i = 0; i < 4; i++) {
        int id = tid + i * 256;
        int row = id >> 3, c = id & 7;
        uint32_t dst = sbuf + G1_TILEB + row * G1_ROWB + c * 16;
        const __half* src = g_sfeatT + (size_t)(n0 + row) * N_NODES + k0 + c * 8;
        CP_ASYNC_16(dst, src);
    }
}

__global__ void __launch_bounds__(256, 2) gemm1_piece_kernel(int S) {
    extern __shared__ __align__(128) char smem[];
    const uint32_t sb = smem_to_u32(smem);
    const int tid = threadIdx.x;
    const int lane = tid & 31;
    const int wid = tid >> 5;
    const int p = blockIdx.x;

    const int g0 = p * S;
    if (g0 >= G1_GKT) return;
    int g1e = g0 + S; if (g1e > G1_GKT) g1e = G1_GKT;
    const int t0 = g0 >> 8;
    const int t1 = (g1e - 1) >> 8;

    const int wm0 = (wid >> 2) * 64;
    const int wn0 = (wid & 3) * 32;

    uint32_t aBase0, bBase0;
    {
        const int seg = lane >> 3;
        const int rA = (lane & 7) + ((seg & 1) << 3);
        const int cA = seg >> 1;
        aBase0 = sb + (uint32_t)(wm0 + rA) * G1_ROWB + cA * 16;
        const int rB = (lane & 7) + ((seg >> 1) << 3);
        const int cB = seg & 1;
        bBase0 = sb + G1_TILEB + (uint32_t)(wn0 + rB) * G1_ROWB + cB * 16;
    }

    const int r = lane >> 2;
    const int c2 = (lane & 3) * 2;

    #pragma unroll 1
    for (int t = t0; t <= t1; t++) {
        const int m0 = (t >> 1) * 128;
        const int n0 = (t & 1) * 128;
        const int tks = t << 8;
        const int ks = (g0 > tks) ? (g0 - tks) : 0;
        const int ke = (g1e < tks + 256) ? (g1e - tks) : 256;
        const int L = ke - ks;

        float acc[4][4][4];
        #pragma unroll
        for (int i = 0; i < 4; i++)
            #pragma unroll
            for (int j = 0; j < 4; j++)
                #pragma unroll
                for (int q = 0; q < 4; q++) acc[i][j][q] = 0.f;

        __syncthreads();   // smem ring reuse across segments

        // prologue (L >= 1 always)
        g1_load_stage(sb + 0 * G1_STAGEB, m0, n0, ks + 0, tid);
        CP_ASYNC_COMMIT();
        if (L > 1) g1_load_stage(sb + 1 * G1_STAGEB, m0, n0, ks + 1, tid);
        CP_ASYNC_COMMIT();

        int stage = 0;
        int ns = 2;
        #pragma unroll 1
        for (int k = 0; k < L; k++) {
            // WAIT_1 is only safe when a REAL group trails this stage's commit;
            // on the final iteration drain fully (fixes short-segment race).
            if (k == L - 1) { CP_ASYNC_WAIT_0(); } else { CP_ASYNC_WAIT_1(); }
            __syncthreads();

            if (k + 2 < L)
                g1_load_stage(sb + ns * G1_STAGEB, m0, n0, ks + k + 2, tid);
            CP_ASYNC_COMMIT();

            const uint32_t aAddr = aBase0 + stage * G1_STAGEB;
            const uint32_t bAddr = bBase0 + stage * G1_STAGEB;

            #pragma unroll
            for (int kq = 0; kq < 4; kq++) {
                uint32_t a[4][4], b[4][2];
                #pragma unroll
                for (int i = 0; i < 4; i++)
                    LDSM_X4(a[i][0], a[i][1], a[i][2], a[i][3],
                            aAddr + i * (16 * G1_ROWB) + kq * 32);
                #pragma unroll
                for (int j = 0; j < 2; j++)
                    LDSM_X4(b[2 * j][0], b[2 * j][1], b[2 * j + 1][0], b[2 * j + 1][1],
                            bAddr + j * (16 * G1_ROWB) + kq * 32);
                #pragma unroll
                for (int i = 0; i < 4; i++)
                    #pragma unroll
                    for (int j = 0; j < 4; j++)
                        MMA_F16(acc[i][j], a[i], b[j]);
            }

            stage++; if (stage == 3) stage = 0;
            ns++;    if (ns == 3)    ns = 0;
        }

        // write fp32 partials for this segment
        const int seg = t - t0;
        float* dst = g_part + (((size_t)p * 2 + seg) << 14);
        #pragma unroll
        for (int i = 0; i < 4; i++) {
            #pragma unroll
            for (int half = 0; half < 2; half++) {
                const int ml = wm0 + i * 16 + r + half * 8;
                #pragma unroll
                for (int j = 0; j < 4; j++) {
                    const int nl = wn0 + j * 8 + c2;
                    float2 v;
                    v.x = acc[i][j][half * 2 + 0];
                    v.y = acc[i][j][half * 2 + 1];
                    *reinterpret_cast<float2*>(&dst[ml * 128 + nl]) = v;
                }
            }
        }
    }
}

// ---------------- kernel 3b: combine partials + epilogue ---------------------
// grid 256 tiles x 256 threads; thread owns half a tile row (64 els).
// aggh = fp16(dinv_m * sum + dinv_m^2 * feat)
__global__ void __launch_bounds__(256) gemm1_combine_kernel(const float* __restrict__ feat,
                                                            int S) {
    const int t = blockIdx.x;
    const int tid = threadIdx.x;
    const int m0 = (t >> 1) * 128;
    const int n0 = (t & 1) * 128;
    const int ml = tid >> 1;
    const int nl0 = (tid & 1) * 64;

    const int gt0 = t << 8;
    const int p0 = gt0 / S;
    const int p1 = (gt0 + 255) / S;

    float4 sum[16];
    #pragma unroll
    for (int i = 0; i < 16; i++) sum[i] = make_float4(0.f, 0.f, 0.f, 0.f);

    for (int p = p0; p <= p1; p++) {
        const int seg = t - ((p * S) >> 8);
        const float4* src = reinterpret_cast<const float4*>(
            g_part + (((size_t)p * 2 + seg) << 14) + ml * 128 + nl0);
        #pragma unroll
        for (int i = 0; i < 16; i++) {
            float4 v = src[i];
            sum[i].x += v.x; sum[i].y += v.y; sum[i].z += v.z; sum[i].w += v.w;
        }
    }

    const int m = m0 + ml;
    const float di = g_dinv[m];
    const float di2 = di * di;
    const float4* fsrc = reinterpret_cast<const float4*>(
        feat + (size_t)m * F_DIM + n0 + nl0);
    uint2* dsth = reinterpret_cast<uint2*>(
        g_aggh + (size_t)m * F_DIM + n0 + nl0);
    #pragma unroll
    for (int i = 0; i < 16; i += 2) {
        float4 f0 = fsrc[i], f1 = fsrc[i + 1];
        float4 s0 = sum[i], s1 = sum[i + 1];
        uint2 o0, o1;
        o0.x = h2_bits(__floats2half2_rn(di * s0.x + di2 * f0.x, di * s0.y + di2 * f0.y));
        o0.y = h2_bits(__floats2half2_rn(di * s0.z + di2 * f0.z, di * s0.w + di2 * f0.w));
        o1.x = h2_bits(__floats2half2_rn(di * s1.x + di2 * f1.x, di * s1.y + di2 * f1.y));
        o1.y = h2_bits(__floats2half2_rn(di * s1.z + di2 * f1.z, di * s1.w + di2 * f1.w));
        dsth[i / 2 * 2 + 0] = o0;
        dsth[i / 2 * 2 + 1] = o1;
    }
}

// ---------------- kernel 4: out = l2norm_rows(relu(aggh @ Wh^T)) -------------
#define G2_BK      64
#define G2_KT      (F_DIM / G2_BK)              /* 4 */
#define G2_ROWB    144
#define G2_TILEA   (64 * G2_ROWB)               /* 9216 */
#define G2_TILEB   (256 * G2_ROWB)              /* 36864 */
#define G2_STAGEB  (G2_TILEA + G2_TILEB)        /* 46080 */
#define G2_SMEM    (2 * G2_STAGEB + 256)        /* 92416 (incl ssq) */

__device__ __forceinline__ void g2_load_stage(uint32_t sbuf, int m0, int kt, int tid) {
    const int k0 = kt * G2_BK;
    #pragma unroll
    for (int i = 0; i < 2; i++) {
        int id = tid + i * 256;
        int row = id >> 3, c = id & 7;
        uint32_t dst = sbuf + row * G2_ROWB + c * 16;
        const __half* src = g_aggh + (size_t)(m0 + row) * F_DIM + k0 + c * 8;
        CP_ASYNC_16(dst, src);
    }
    #pragma unroll
    for (int i = 0; i < 8; i++) {
        int id = tid + i * 256;
        int row = id >> 3, c = id & 7;
        uint32_t dst = sbuf + G2_TILEA + row * G2_ROWB + c * 16;
        const __half* src = g_Wh + (size_t)row * F_DIM + k0 + c * 8;
        CP_ASYNC_16(dst, src);
    }
}

__global__ void __launch_bounds__(256, 2) gemm2h_norm_kernel(float* __restrict__ out) {
    extern __shared__ __align__(128) char smem[];
    const uint32_t sb = smem_to_u32(smem);
    float* s_ssq = reinterpret_cast<float*>(smem + 2 * G2_STAGEB);
    const int tid = threadIdx.x;
    const int lane = tid & 31;
    const int wid = tid >> 5;
    const int m0 = blockIdx.x * 64;
    const int wm0 = (wid >> 2) * 32;
    const int wn0 = (wid & 3) * 64;

    if (tid < 64) s_ssq[tid] = 0.f;

    float acc[2][8][4];
    #pragma unroll
    for (int i = 0; i < 2; i++)
        #pragma unroll
        for (int j = 0; j < 8; j++)
            #pragma unroll
            for (int q = 0; q < 4; q++) acc[i][j][q] = 0.f;

    uint32_t aBase0, bBase0;
    {
        const int seg = lane >> 3;
        const int rA = (lane & 7) + ((seg & 1) << 3);
        const int cA = seg >> 1;
        aBase0 = sb + (uint32_t)(wm0 + rA) * G2_ROWB + cA * 16;
        const int rB = (lane & 7) + ((seg >> 1) << 3);
        const int cB = seg & 1;
        bBase0 = sb + G2_TILEA + (uint32_t)(wn0 + rB) * G2_ROWB + cB * 16;
    }

    g2_load_stage(sb + 0 * G2_STAGEB, m0, 0, tid);
    CP_ASYNC_COMMIT();

    #pragma unroll
    for (int kt = 0; kt < G2_KT; kt++) {
        CP_ASYNC_WAIT_0();
        __syncthreads();

        const int nk = kt + 1;
        if (nk < G2_KT) {
            g2_load_stage(sb + (nk & 1) * G2_STAGEB, m0, nk, tid);
            CP_ASYNC_COMMIT();
        }

        const uint32_t aAddr = aBase0 + (kt & 1) * G2_STAGEB;
        const uint32_t bAddr = bBase0 + (kt & 1) * G2_STAGEB;

        #pragma unroll
        for (int ks = 0; ks < 4; ks++) {
            uint32_t a[2][4], b[8][2];
            #pragma unroll
            for (int i = 0; i < 2; i++)
                LDSM_X4(a[i][0], a[i][1], a[i][2], a[i][3],
                        aAddr + i * (16 * G2_ROWB) + ks * 32);
            #pragma unroll
            for (int j = 0; j < 4; j++)
                LDSM_X4(b[2 * j][0], b[2 * j][1], b[2 * j + 1][0], b[2 * j + 1][1],
                        bAddr + j * (16 * G2_ROWB) + ks * 32);
            #pragma unroll
            for (int i = 0; i < 2; i++)
                #pragma unroll
                for (int j = 0; j < 8; j++)
                    MMA_F16(acc[i][j], a[i], b[j]);
        }
    }

    const int r = lane >> 2;
    #pragma unroll
    for (int i = 0; i < 2; i++) {
        #pragma unroll
        for (int half = 0; half < 2; half++) {
            float p = 0.f;
            #pragma unroll
            for (int j = 0; j < 8; j++) {
                float v0 = fmaxf(acc[i][j][half * 2 + 0], 0.f);
                float v1 = fmaxf(acc[i][j][half * 2 + 1], 0.f);
                acc[i][j][half * 2 + 0] = v0;
                acc[i][j][half * 2 + 1] = v1;
                p = fmaf(v0, v0, fmaf(v1, v1, p));
            }
            p += __shfl_xor_sync(0xffffffffu, p, 1);
            p += __shfl_xor_sync(0xffffffffu, p, 2);
            if ((lane & 3) == 0)
                atomicAdd(&s_ssq[wm0 + i * 16 + r + half * 8], p);
        }
    }
    __syncthreads();

    const int c2 = (lane & 3) * 2;
    #pragma unroll
    for (int i = 0; i < 2; i++) {
        #pragma unroll
        for (int half = 0; half < 2; half++) {
            const int ml = wm0 + i * 16 + r + half * 8;
            const int m = m0 + ml;
            float nrm = sqrtf(s_ssq[ml]);
            float sc = 1.0f / fmaxf(nrm, EPS_NORM);
            #pragma unroll
            for (int j = 0; j < 8; j++) {
                const int n = wn0 + j * 8 + c2;
                float2 o;
                o.x = acc[i][j][half * 2 + 0] * sc;
                o.y = acc[i][j][half * 2 + 1] * sc;
                *reinterpret_cast<float2*>(&out[(size_t)m * F_DIM + n]) = o;
            }
        }
    }
}

// ---------------- host launch -------------------------------------------------
extern "C" void kernel_launch(void* const* d_in, const int* in_sizes, int n_in,
                              void* d_out, int out_size) {
    const float* feat = nullptr;
    const float* A = nullptr;
    const float* W = nullptr;
    for (int i = 0; i < n_in; i++) {
        long long sz = (long long)in_sizes[i];
        if (sz == (long long)N_NODES * N_NODES)      A    = (const float*)d_in[i];
        else if (sz == (long long)N_NODES * F_DIM)   feat = (const float*)d_in[i];
        else if (sz == (long long)F_DIM * F_DIM)     W    = (const float*)d_in[i];
    }
    float* out = (float*)d_out;

    static int S = 0;
    static int npieces = 0;
    if (!S) {
        int nsm = 0;
        cudaDeviceGetAttribute(&nsm, cudaDevAttrMultiProcessorCount, 0);
        if (nsm <= 0) nsm = 148;
        int target = 2 * nsm;                      // 2 piece-slots per SM
        S = (G1_GKT + target - 1) / target;        // 216 on 152 SMs
        if (S > 256) S = 256;                      // piece spans <= 2 tiles
        npieces = (G1_GKT + S - 1) / S;            // <= MAX_PIECES
        if (npieces > MAX_PIECES) { S = (G1_GKT + MAX_PIECES - 1) / MAX_PIECES;
                                    npieces = (G1_GKT + S - 1) / S; }
        cudaFuncSetAttribute(gemm1_piece_kernel,
                             cudaFuncAttributeMaxDynamicSharedMemorySize, G1_SMEM);
        cudaFuncSetAttribute(gemm2h_norm_kernel,
                             cudaFuncAttributeMaxDynamicSharedMemorySize, G2_SMEM);
    }

    // 1. degrees -> dinv, plus A -> fp16 copy
    rowsum_convert_kernel<<<N_NODES, 256>>>(A);
    // 2. merged transposes: z=0 feat (scaled), z=1 W
    {
        dim3 grid(N_NODES / 32, F_DIM / 32, 2);
        transpose_all_kernel<<<grid, dim3(32, 8)>>>(feat, W);
    }
    // 3. split-K piece GEMM (perfect 2-per-SM packing) + combine/epilogue
    gemm1_piece_kernel<<<npieces, 256, G1_SMEM>>>(S);
    gemm1_combine_kernel<<<256, 256>>>(feat, S);
    // 4. fp16 projection + relu + row L2 normalize
    gemm2h_norm_kernel<<<N_NODES / 64, 256, G2_SMEM>>>(out);
}

// round 16
// speedup vs baseline: 1.3323x; 1.0160x over previous
#include <cuda_runtime.h>
#include <cuda_fp16.h>
#include <math.h>
#include <stdint.h>

#define N_NODES 16384
#define F_DIM   256
#define EPS_NORM 1e-12f

// ---------------- scratch (allocation-free: __device__ globals) ----------------
__device__ float  g_dinv[N_NODES];                   // 1/sqrt(deg)
__device__ __half g_Ah[(size_t)N_NODES * N_NODES];   // fp16(A), row-major (512 MB)
__device__ __half g_sfeatT[F_DIM * N_NODES];         // fp16(dinv[k]*feat[k][n]), [n][k]
__device__ __half g_aggh[N_NODES * F_DIM];           // fp16 feat_agg, [m][k] K-major
__device__ __half g_Wh[F_DIM * F_DIM];               // fp16(W^T), [n][k] K-major
// split-K partial sums: up to 320 pieces x 2 segments x 128x128 fp32 tile
#define MAX_PIECES 320
__device__ float  g_part[(size_t)MAX_PIECES * 2 * 16384];

// ============================ PTX helpers (sm_80+ portable) ==================
__device__ __forceinline__ uint32_t smem_to_u32(const void* p) {
    uint32_t a;
    asm("{ .reg .u64 t; cvta.to.shared.u64 t, %1; cvt.u32.u64 %0, t; }" : "=r"(a) : "l"(p));
    return a;
}

__device__ __forceinline__ uint32_t h2_bits(__half2 h) {
    return *reinterpret_cast<uint32_t*>(&h);
}

#define LDSM_X4(r0, r1, r2, r3, addr) \
    asm volatile("ldmatrix.sync.aligned.m8n8.x4.shared.b16 {%0,%1,%2,%3}, [%4];" \
        : "=r"(r0), "=r"(r1), "=r"(r2), "=r"(r3) : "r"(addr))

#define MMA_F16(d, a, b) \
    asm volatile("mma.sync.aligned.m16n8k16.row.col.f32.f16.f16.f32 " \
        "{%0,%1,%2,%3}, {%4,%5,%6,%7}, {%8,%9}, {%0,%1,%2,%3};" \
        : "+f"((d)[0]), "+f"((d)[1]), "+f"((d)[2]), "+f"((d)[3]) \
        : "r"((a)[0]), "r"((a)[1]), "r"((a)[2]), "r"((a)[3]), \
          "r"((b)[0]), "r"((b)[1]))

#define CP_ASYNC_16(dst, src) \
    asm volatile("cp.async.cg.shared.global [%0], [%1], 16;" :: "r"(dst), "l"(src))
#define CP_ASYNC_COMMIT() asm volatile("cp.async.commit_group;" ::: "memory")
#define CP_ASYNC_WAIT_1() asm volatile("cp.async.wait_group 1;" ::: "memory")
#define CP_ASYNC_WAIT_0() asm volatile("cp.async.wait_group 0;" ::: "memory")

// ---------------- kernel 1: rowsum + fp16 convert of A -----------------------
__global__ void __launch_bounds__(256) rowsum_convert_kernel(const float* __restrict__ A) {
    const int row = blockIdx.x;
    const float4* arow = reinterpret_cast<const float4*>(A + (size_t)row * N_NODES);
    uint4* hrow = reinterpret_cast<uint4*>(g_Ah + (size_t)row * N_NODES);
    const int t = threadIdx.x;
    float s = 0.f;
    #pragma unroll
    for (int j = 0; j < 8; j++) {
        int f4 = j * 512 + t * 2;
        float4 v0 = arow[f4];
        float4 v1 = arow[f4 + 1];
        s += ((v0.x + v0.y) + (v0.z + v0.w)) + ((v1.x + v1.y) + (v1.z + v1.w));
        uint4 o;
        o.x = h2_bits(__floats2half2_rn(v0.x, v0.y));
        o.y = h2_bits(__floats2half2_rn(v0.z, v0.w));
        o.z = h2_bits(__floats2half2_rn(v1.x, v1.y));
        o.w = h2_bits(__floats2half2_rn(v1.z, v1.w));
        hrow[j * 256 + t] = o;
    }
    __shared__ float red[8];
    #pragma unroll
    for (int o = 16; o > 0; o >>= 1) s += __shfl_down_sync(0xffffffffu, s, o);
    if ((t & 31) == 0) red[t >> 5] = s;
    __syncthreads();
    if (t < 32) {
        s = (t < 8) ? red[t] : 0.f;
        #pragma unroll
        for (int o = 4; o > 0; o >>= 1) s += __shfl_down_sync(0xffffffffu, s, o);
        if (t == 0) g_dinv[row] = rsqrtf(s + 1.0f);
    }
}

// ---------------- kernel 2: merged transposes --------------------------------
__global__ void __launch_bounds__(256) transpose_all_kernel(const float* __restrict__ feat,
                                                            const float* __restrict__ W) {
    __shared__ float tbuf[32][33];
    const int z  = blockIdx.z;
    const int k0 = blockIdx.x * 32;
    const int n0 = blockIdx.y * 32;
    const int tx = threadIdx.x, ty = threadIdx.y;
    if (z == 0) {
        #pragma unroll
        for (int i = 0; i < 4; i++) {
            int k = k0 + ty + i * 8;
            tbuf[ty + i * 8][tx] = g_dinv[k] * feat[(size_t)k * F_DIM + n0 + tx];
        }
        __syncthreads();
        #pragma unroll
        for (int i = 0; i < 4; i++) {
            int n = n0 + ty + i * 8;
            g_sfeatT[(size_t)n * N_NODES + k0 + tx] = __float2half_rn(tbuf[tx][ty + i * 8]);
        }
    } else {
        if (k0 >= F_DIM) return;
        #pragma unroll
        for (int i = 0; i < 4; i++) {
            int k = k0 + ty + i * 8;
            tbuf[ty + i * 8][tx] = W[(size_t)k * F_DIM + n0 + tx];
        }
        __syncthreads();
        #pragma unroll
        for (int i = 0; i < 4; i++) {
            int n = n0 + ty + i * 8;
            g_Wh[(size_t)n * F_DIM + k0 + tx] = __float2half_rn(tbuf[tx][ty + i * 8]);
        }
    }
}

// ---------------- kernel 3: GEMM1 pieces (continuous split-K packing) --------
// Global iteration space: 256 tiles (t = tm*2 + tn, tile 128x128) x 256 kt.
// Piece p handles global kt range [p*S, (p+1)*S), S <= 256 -> spans <= 2 tiles.
#define G1_BK       64
#define G1_ROWB     144                         /* 64 halves (128B) + 16B pad */
#define G1_TILEB    (128 * G1_ROWB)             /* 18432 per operand tile */
#define G1_STAGEB   (2 * G1_TILEB)              /* 36864 */
#define G1_SMEM     (3 * G1_STAGEB)             /* 110592 */
#define G1_GKT      (256 * 256)                 /* 65536 global kt units */

__device__ __forceinline__ void g1_load_stage(uint32_t sbuf, int m0, int n0, int kt, int tid) {
    const int k0 = kt * G1_BK;
    #pragma unroll
    for (int i = 0; i < 4; i++) {
        int id = tid + i * 256;
        int row = id >> 3, c = id & 7;
        uint32_t dst = sbuf + row * G1_ROWB + c * 16;
        const __half* src = g_Ah + (size_t)(m0 + row) * N_NODES + k0 + c * 8;
        CP_ASYNC_16(dst, src);
    }
    #pragma unroll
    for (int i = 0; i < 4; i++) {
        int id = tid + i * 256;
        int row = id >> 3, c = id & 7;
        uint32_t dst = sbuf + G1_TILEB + row * G1_ROWB + c * 16;
        const __half* src = g_sfeatT + (size_t)(n0 + row) * N_NODES + k0 + c * 8;
        CP_ASYNC_16(dst, src);
    }
}

__global__ void __launch_bounds__(256, 2) gemm1_piece_kernel(int S) {
    extern __shared__ __align__(128) char smem[];
    const uint32_t sb = smem_to_u32(smem);
    const int tid = threadIdx.x;
    const int lane = tid & 31;
    const int wid = tid >> 5;
    const int p = blockIdx.x;

    const int g0 = p * S;
    if (g0 >= G1_GKT) return;
    int g1e = g0 + S; if (g1e > G1_GKT) g1e = G1_GKT;
    const int t0 = g0 >> 8;
    const int t1 = (g1e - 1) >> 8;

    const int wm0 = (wid >> 2) * 64;
    const int wn0 = (wid & 3) * 32;

    uint32_t aBase0, bBase0;
    {
        const int seg = lane >> 3;
        const int rA = (lane & 7) + ((seg & 1) << 3);
        const int cA = seg >> 1;
        aBase0 = sb + (uint32_t)(wm0 + rA) * G1_ROWB + cA * 16;
        const int rB = (lane & 7) + ((seg >> 1) << 3);
        const int cB = seg & 1;
        bBase0 = sb + G1_TILEB + (uint32_t)(wn0 + rB) * G1_ROWB + cB * 16;
    }

    const int r = lane >> 2;
    const int c2 = (lane & 3) * 2;

    #pragma unroll 1
    for (int t = t0; t <= t1; t++) {
        const int m0 = (t >> 1) * 128;
        const int n0 = (t & 1) * 128;
        const int tks = t << 8;
        const int ks = (g0 > tks) ? (g0 - tks) : 0;
        const int ke = (g1e < tks + 256) ? (g1e - tks) : 256;
        const int L = ke - ks;

        float acc[4][4][4];
        #pragma unroll
        for (int i = 0; i < 4; i++)
            #pragma unroll
            for (int j = 0; j < 4; j++)
                #pragma unroll
                for (int q = 0; q < 4; q++) acc[i][j][q] = 0.f;

        __syncthreads();   // smem ring reuse across segments

        g1_load_stage(sb + 0 * G1_STAGEB, m0, n0, ks + 0, tid);
        CP_ASYNC_COMMIT();
        if (L > 1) g1_load_stage(sb + 1 * G1_STAGEB, m0, n0, ks + 1, tid);
        CP_ASYNC_COMMIT();

        int stage = 0;
        int ns = 2;
        #pragma unroll 1
        for (int k = 0; k < L; k++) {
            if (k == L - 1) { CP_ASYNC_WAIT_0(); } else { CP_ASYNC_WAIT_1(); }
            __syncthreads();

            if (k + 2 < L)
                g1_load_stage(sb + ns * G1_STAGEB, m0, n0, ks + k + 2, tid);
            CP_ASYNC_COMMIT();

            const uint32_t aAddr = aBase0 + stage * G1_STAGEB;
            const uint32_t bAddr = bBase0 + stage * G1_STAGEB;

            #pragma unroll
            for (int kq = 0; kq < 4; kq++) {
                uint32_t a[4][4], b[4][2];
                #pragma unroll
                for (int i = 0; i < 4; i++)
                    LDSM_X4(a[i][0], a[i][1], a[i][2], a[i][3],
                            aAddr + i * (16 * G1_ROWB) + kq * 32);
                #pragma unroll
                for (int j = 0; j < 2; j++)
                    LDSM_X4(b[2 * j][0], b[2 * j][1], b[2 * j + 1][0], b[2 * j + 1][1],
                            bAddr + j * (16 * G1_ROWB) + kq * 32);
                #pragma unroll
                for (int i = 0; i < 4; i++)
                    #pragma unroll
                    for (int j = 0; j < 4; j++)
                        MMA_F16(acc[i][j], a[i], b[j]);
            }

            stage++; if (stage == 3) stage = 0;
            ns++;    if (ns == 3)    ns = 0;
        }

        // write fp32 partials for this segment
        const int seg = t - t0;
        float* dst = g_part + (((size_t)p * 2 + seg) << 14);
        #pragma unroll
        for (int i = 0; i < 4; i++) {
            #pragma unroll
            for (int half = 0; half < 2; half++) {
                const int ml = wm0 + i * 16 + r + half * 8;
                #pragma unroll
                for (int j = 0; j < 4; j++) {
                    const int nl = wn0 + j * 8 + c2;
                    float2 v;
                    v.x = acc[i][j][half * 2 + 0];
                    v.y = acc[i][j][half * 2 + 1];
                    *reinterpret_cast<float2*>(&dst[ml * 128 + nl]) = v;
                }
            }
        }
    }
}

// ---------------- kernel 3b: combine partials + epilogue ---------------------
// grid 1024 (tile t = b>>2, 32-row slab = b&3) x 256 threads;
// thread owns 16 contiguous floats: row = slab*32 + tid/8, col seg = (tid&7)*16.
// aggh = fp16(dinv_m * sum + dinv_m^2 * feat)
__global__ void __launch_bounds__(256) gemm1_combine_kernel(const float* __restrict__ feat,
                                                            int S) {
    const int b = blockIdx.x;
    const int t = b >> 2;
    const int slab = b & 3;
    const int tid = threadIdx.x;
    const int m0 = (t >> 1) * 128;
    const int n0 = (t & 1) * 128;
    const int ml = slab * 32 + (tid >> 3);
    const int nl0 = (tid & 7) * 16;

    const int gt0 = t << 8;
    const int p0 = gt0 / S;
    const int p1 = (gt0 + 255) / S;

    float4 sum[4];
    #pragma unroll
    for (int i = 0; i < 4; i++) sum[i] = make_float4(0.f, 0.f, 0.f, 0.f);

    for (int p = p0; p <= p1; p++) {
        const int seg = t - ((p * S) >> 8);
        const float4* src = reinterpret_cast<const float4*>(
            g_part + (((size_t)p * 2 + seg) << 14) + ml * 128 + nl0);
        #pragma unroll
        for (int i = 0; i < 4; i++) {
            float4 v = src[i];
            sum[i].x += v.x; sum[i].y += v.y; sum[i].z += v.z; sum[i].w += v.w;
        }
    }

    const int m = m0 + ml;
    const float di = g_dinv[m];
    const float di2 = di * di;
    const float4* fsrc = reinterpret_cast<const float4*>(
        feat + (size_t)m * F_DIM + n0 + nl0);
    uint2* dsth = reinterpret_cast<uint2*>(
        g_aggh + (size_t)m * F_DIM + n0 + nl0);
    #pragma unroll
    for (int i = 0; i < 4; i++) {
        float4 f0 = fsrc[i];
        float4 s0 = sum[i];
        uint2 o0;
        o0.x = h2_bits(__floats2half2_rn(di * s0.x + di2 * f0.x, di * s0.y + di2 * f0.y));
        o0.y = h2_bits(__floats2half2_rn(di * s0.z + di2 * f0.z, di * s0.w + di2 * f0.w));
        dsth[i] = o0;
    }
}

// ---------------- kernel 4: out = l2norm_rows(relu(aggh @ Wh^T)) -------------
#define G2_BK      64
#define G2_KT      (F_DIM / G2_BK)              /* 4 */
#define G2_ROWB    144
#define G2_TILEA   (64 * G2_ROWB)               /* 9216 */
#define G2_TILEB   (256 * G2_ROWB)              /* 36864 */
#define G2_STAGEB  (G2_TILEA + G2_TILEB)        /* 46080 */
#define G2_SMEM    (2 * G2_STAGEB + 256)        /* 92416 (incl ssq) */

__device__ __forceinline__ void g2_load_stage(uint32_t sbuf, int m0, int kt, int tid) {
    const int k0 = kt * G2_BK;
    #pragma unroll
    for (int i = 0; i < 2; i++) {
        int id = tid + i * 256;
        int row = id >> 3, c = id & 7;
        uint32_t dst = sbuf + row * G2_ROWB + c * 16;
        const __half* src = g_aggh + (size_t)(m0 + row) * F_DIM + k0 + c * 8;
        CP_ASYNC_16(dst, src);
    }
    #pragma unroll
    for (int i = 0; i < 8; i++) {
        int id = tid + i * 256;
        int row = id >> 3, c = id & 7;
        uint32_t dst = sbuf + G2_TILEA + row * G2_ROWB + c * 16;
        const __half* src = g_Wh + (size_t)row * F_DIM + k0 + c * 8;
        CP_ASYNC_16(dst, src);
    }
}

__global__ void __launch_bounds__(256, 2) gemm2h_norm_kernel(float* __restrict__ out) {
    extern __shared__ __align__(128) char smem[];
    const uint32_t sb = smem_to_u32(smem);
    float* s_ssq = reinterpret_cast<float*>(smem + 2 * G2_STAGEB);
    const int tid = threadIdx.x;
    const int lane = tid & 31;
    const int wid = tid >> 5;
    const int m0 = blockIdx.x * 64;
    const int wm0 = (wid >> 2) * 32;
    const int wn0 = (wid & 3) * 64;

    if (tid < 64) s_ssq[tid] = 0.f;

    float acc[2][8][4];
    #pragma unroll
    for (int i = 0; i < 2; i++)
        #pragma unroll
        for (int j = 0; j < 8; j++)
            #pragma unroll
            for (int q = 0; q < 4; q++) acc[i][j][q] = 0.f;

    uint32_t aBase0, bBase0;
    {
        const int seg = lane >> 3;
        const int rA = (lane & 7) + ((seg & 1) << 3);
        const int cA = seg >> 1;
        aBase0 = sb + (uint32_t)(wm0 + rA) * G2_ROWB + cA * 16;
        const int rB = (lane & 7) + ((seg >> 1) << 3);
        const int cB = seg & 1;
        bBase0 = sb + G2_TILEA + (uint32_t)(wn0 + rB) * G2_ROWB + cB * 16;
    }

    g2_load_stage(sb + 0 * G2_STAGEB, m0, 0, tid);
    CP_ASYNC_COMMIT();

    #pragma unroll
    for (int kt = 0; kt < G2_KT; kt++) {
        CP_ASYNC_WAIT_0();
        __syncthreads();

        const int nk = kt + 1;
        if (nk < G2_KT) {
            g2_load_stage(sb + (nk & 1) * G2_STAGEB, m0, nk, tid);
            CP_ASYNC_COMMIT();
        }

        const uint32_t aAddr = aBase0 + (kt & 1) * G2_STAGEB;
        const uint32_t bAddr = bBase0 + (kt & 1) * G2_STAGEB;

        #pragma unroll
        for (int ks = 0; ks < 4; ks++) {
            uint32_t a[2][4], b[8][2];
            #pragma unroll
            for (int i = 0; i < 2; i++)
                LDSM_X4(a[i][0], a[i][1], a[i][2], a[i][3],
                        aAddr + i * (16 * G2_ROWB) + ks * 32);
            #pragma unroll
            for (int j = 0; j < 4; j++)
                LDSM_X4(b[2 * j][0], b[2 * j][1], b[2 * j + 1][0], b[2 * j + 1][1],
                        bAddr + j * (16 * G2_ROWB) + ks * 32);
            #pragma unroll
            for (int i = 0; i < 2; i++)
                #pragma unroll
                for (int j = 0; j < 8; j++)
                    MMA_F16(acc[i][j], a[i], b[j]);
        }
    }

    const int r = lane >> 2;
    #pragma unroll
    for (int i = 0; i < 2; i++) {
        #pragma unroll
        for (int half = 0; half < 2; half++) {
            float p = 0.f;
            #pragma unroll
            for (int j = 0; j < 8; j++) {
                float v0 = fmaxf(acc[i][j][half * 2 + 0], 0.f);
                float v1 = fmaxf(acc[i][j][half * 2 + 1], 0.f);
                acc[i][j][half * 2 + 0] = v0;
                acc[i][j][half * 2 + 1] = v1;
                p = fmaf(v0, v0, fmaf(v1, v1, p));
            }
            p += __shfl_xor_sync(0xffffffffu, p, 1);
            p += __shfl_xor_sync(0xffffffffu, p, 2);
            if ((lane & 3) == 0)
                atomicAdd(&s_ssq[wm0 + i * 16 + r + half * 8], p);
        }
    }
    __syncthreads();

    const int c2 = (lane & 3) * 2;
    #pragma unroll
    for (int i = 0; i < 2; i++) {
        #pragma unroll
        for (int half = 0; half < 2; half++) {
            const int ml = wm0 + i * 16 + r + half * 8;
            const int m = m0 + ml;
            float nrm = sqrtf(s_ssq[ml]);
            float sc = 1.0f / fmaxf(nrm, EPS_NORM);
            #pragma unroll
            for (int j = 0; j < 8; j++) {
                const int n = wn0 + j * 8 + c2;
                float2 o;
                o.x = acc[i][j][half * 2 + 0] * sc;
                o.y = acc[i][j][half * 2 + 1] * sc;
                *reinterpret_cast<float2*>(&out[(size_t)m * F_DIM + n]) = o;
            }
        }
    }
}

// ---------------- host launch -------------------------------------------------
extern "C" void kernel_launch(void* const* d_in, const int* in_sizes, int n_in,
                              void* d_out, int out_size) {
    const float* feat = nullptr;
    const float* A = nullptr;
    const float* W = nullptr;
    for (int i = 0; i < n_in; i++) {
        long long sz = (long long)in_sizes[i];
        if (sz == (long long)N_NODES * N_NODES)      A    = (const float*)d_in[i];
        else if (sz == (long long)N_NODES * F_DIM)   feat = (const float*)d_in[i];
        else if (sz == (long long)F_DIM * F_DIM)     W    = (const float*)d_in[i];
    }
    float* out = (float*)d_out;

    static int S = 0;
    static int npieces = 0;
    if (!S) {
        int nsm = 0;
        cudaDeviceGetAttribute(&nsm, cudaDevAttrMultiProcessorCount, 0);
        if (nsm <= 0) nsm = 148;
        int target = 2 * nsm;                      // 2 piece-slots per SM
        S = (G1_GKT + target - 1) / target;        // 216 on 152 SMs
        if (S > 256) S = 256;                      // piece spans <= 2 tiles
        npieces = (G1_GKT + S - 1) / S;            // <= MAX_PIECES
        if (npieces > MAX_PIECES) { S = (G1_GKT + MAX_PIECES - 1) / MAX_PIECES;
                                    npieces = (G1_GKT + S - 1) / S; }
        cudaFuncSetAttribute(gemm1_piece_kernel,
                             cudaFuncAttributeMaxDynamicSharedMemorySize, G1_SMEM);
        cudaFuncSetAttribute(gemm2h_norm_kernel,
                             cudaFuncAttributeMaxDynamicSharedMemorySize, G2_SMEM);
    }

    // 1. degrees -> dinv, plus A -> fp16 copy
    rowsum_convert_kernel<<<N_NODES, 256>>>(A);
    // 2. merged transposes: z=0 feat (scaled), z=1 W
    {
        dim3 grid(N_NODES / 32, F_DIM / 32, 2);
        transpose_all_kernel<<<grid, dim3(32, 8)>>>(feat, W);
    }
    // 3. split-K piece GEMM (perfect 2-per-SM packing) + combine/epilogue
    gemm1_piece_kernel<<<npieces, 256, G1_SMEM>>>(S);
    gemm1_combine_kernel<<<1024, 256>>>(feat, S);
    // 4. fp16 projection + relu + row L2 normalize
    gemm2h_norm_kernel<<<N_NODES / 64, 256, G2_SMEM>>>(out);
}